// round 2
// baseline (speedup 1.0000x reference)
#include <cuda_runtime.h>

#define NB   2
#define SEQ  2048
#define DIM  1024
#define NH   16
#define HD   64
#define MROWS (NB*SEQ)   // 4096

// Scratch (allocation-free rule: __device__ globals)
__device__ float g_q[NB*NH*SEQ*HD];     // [B,H,S,hd]
__device__ float g_k[NB*NH*SEQ*HD];
__device__ float g_v[NB*NH*SEQ*HD];
__device__ float g_att[MROWS*DIM];      // [B,S,H*hd]
__device__ float g_cos[SEQ*(HD/2)];
__device__ float g_sin[SEQ*(HD/2)];

// ---------------------------------------------------------------------------
// RoPE table: angle = s * theta^(-p/32), computed in double for accuracy.
// ---------------------------------------------------------------------------
__global__ void rope_table_kernel() {
    int i = blockIdx.x * blockDim.x + threadIdx.x;
    if (i >= SEQ * (HD/2)) return;
    int s = i >> 5;          // position
    int p = i & 31;          // pair index
    double inv = pow(10000.0, -(double)p / 32.0);
    double a = (double)s * inv;
    g_cos[i] = (float)cos(a);
    g_sin[i] = (float)sin(a);
}

// ---------------------------------------------------------------------------
// NT GEMM: C[m,n] = sum_k A[m,k] * W[n,k] + bias[n]
// BM=BN=64, BK=16, 256 threads, 4x4 micro-tile per thread.
// Thread (tx,ty): rows {ty+16i}, cols {2tx, 2tx+1, 2tx+32, 2tx+33}
//   (adjacent column pairs so RoPE even/odd elements live in one thread).
// MODE 0: Q proj (+RoPE, scatter to g_q [B,H,S,hd])
// MODE 1: K proj (+RoPE, scatter to g_k)
// MODE 2: V proj (scatter to g_v)
// MODE 3: O proj (A = g_att, plain row-major output)
// ---------------------------------------------------------------------------
template<int MODE>
__global__ void __launch_bounds__(256) gemm_nt_kernel(
        const float* __restrict__ A, const float* __restrict__ W,
        const float* __restrict__ bias, float* __restrict__ Cout)
{
    __shared__ __align__(16) float As[16][66];
    __shared__ __align__(16) float Bs[16][66];

    const int tid = threadIdx.x;
    const int tx = tid & 15, ty = tid >> 4;
    const int lr = tid >> 2, lc = (tid & 3) << 2;     // loader: row, 4-col group
    const int row0 = blockIdx.y << 6, col0 = blockIdx.x << 6;

    const float* Abase = (MODE == 3) ? (const float*)g_att : A;
    const float* Ap = Abase + (row0 + lr) * DIM + lc;
    const float* Wp = W + (col0 + lr) * DIM + lc;

    float acc[4][4] = {};

    for (int k0 = 0; k0 < DIM; k0 += 16) {
        float4 av = *(const float4*)(Ap + k0);
        float4 wv = *(const float4*)(Wp + k0);
        As[lc+0][lr] = av.x; As[lc+1][lr] = av.y; As[lc+2][lr] = av.z; As[lc+3][lr] = av.w;
        Bs[lc+0][lr] = wv.x; Bs[lc+1][lr] = wv.y; Bs[lc+2][lr] = wv.z; Bs[lc+3][lr] = wv.w;
        __syncthreads();
        #pragma unroll
        for (int kk = 0; kk < 16; kk++) {
            float a0 = As[kk][ty],    a1 = As[kk][ty+16];
            float a2 = As[kk][ty+32], a3 = As[kk][ty+48];
            float2 b01 = *(const float2*)&Bs[kk][2*tx];
            float2 b23 = *(const float2*)&Bs[kk][2*tx + 32];
            acc[0][0] += a0*b01.x; acc[0][1] += a0*b01.y; acc[0][2] += a0*b23.x; acc[0][3] += a0*b23.y;
            acc[1][0] += a1*b01.x; acc[1][1] += a1*b01.y; acc[1][2] += a1*b23.x; acc[1][3] += a1*b23.y;
            acc[2][0] += a2*b01.x; acc[2][1] += a2*b01.y; acc[2][2] += a2*b23.x; acc[2][3] += a2*b23.y;
            acc[3][0] += a3*b01.x; acc[3][1] += a3*b01.y; acc[3][2] += a3*b23.x; acc[3][3] += a3*b23.y;
        }
        __syncthreads();
    }

    // Epilogue
    if (MODE == 3) {
        #pragma unroll
        for (int i = 0; i < 4; i++) {
            int m = row0 + ty + 16*i;
            #pragma unroll
            for (int g = 0; g < 2; g++) {
                int n = col0 + g*32 + 2*tx;
                float e = acc[i][2*g]   + bias[n];
                float o = acc[i][2*g+1] + bias[n+1];
                *(float2*)&Cout[m*DIM + n] = make_float2(e, o);
            }
        }
    } else {
        float* dst = (MODE == 0) ? g_q : (MODE == 1) ? g_k : g_v;
        const int h = col0 >> 6;   // N=1024, 64-wide block == one head
        #pragma unroll
        for (int i = 0; i < 4; i++) {
            int m = row0 + ty + 16*i;
            int b = m >> 11;       // m / SEQ
            int s = m & (SEQ - 1);
            #pragma unroll
            for (int g = 0; g < 2; g++) {
                int d0 = g*32 + 2*tx;           // even dim within head
                int n = col0 + d0;
                float e = acc[i][2*g]   + bias[n];
                float o = acc[i][2*g+1] + bias[n+1];
                float re, im;
                if (MODE <= 1) {
                    float c  = g_cos[s*32 + (d0 >> 1)];
                    float sn = g_sin[s*32 + (d0 >> 1)];
                    re = e*c - o*sn;
                    im = e*sn + o*c;
                } else {
                    re = e; im = o;
                }
                int idx = ((b*NH + h)*SEQ + s)*HD + d0;
                *(float2*)&dst[idx] = make_float2(re, im);
            }
        }
    }
}

// ---------------------------------------------------------------------------
// Flash attention: one CTA per (batch-head, 64-row q-tile).
// Qs [q][d], Vs [kv][d], KPs dual-use: K-tile transposed [d][kv] for QK^T,
// then P [q][kv] for PV (K smem is dead after the score pass).
// 48KB static smem exactly; thread (tx,ty) owns rows {ty+16i},
// cols {2tx,2tx+1,2tx+32,2tx+33}.
// Tile loads: 64x64 floats = 4096; 256 threads x 4 float4 each
// (col groups lc+16j, j=0..3).  <-- R1 bug fix: previously only j=0 loaded.
// ---------------------------------------------------------------------------
__global__ void __launch_bounds__(256) attn_kernel() {
    __shared__ __align__(16) float Qs[64*64];
    __shared__ __align__(16) float KPs[64*64];
    __shared__ __align__(16) float Vs[64*64];

    const int tid = threadIdx.x;
    const int tx = tid & 15, ty = tid >> 4;
    const int lr = tid >> 2, lc = (tid & 3) << 2;
    const int qt = blockIdx.x, bh = blockIdx.y;

    const float* Qg = g_q + (bh*SEQ + qt*64)*HD;
    const float* Kg = g_k + bh*SEQ*HD;
    const float* Vg = g_v + bh*SEQ*HD;

    {   // Q tile, pre-scaled by hd^-0.5 (full 64 cols: 4 groups)
        const float sc = 0.125f;
        #pragma unroll
        for (int j = 0; j < 4; j++) {
            int c = lc + 16*j;
            float4 q4 = *(const float4*)(Qg + lr*HD + c);
            float* d = &Qs[lr*64 + c];
            d[0] = q4.x*sc; d[1] = q4.y*sc; d[2] = q4.z*sc; d[3] = q4.w*sc;
        }
    }

    float m_i[4] = {-1e30f, -1e30f, -1e30f, -1e30f};
    float l_i[4] = {};
    float o[4][4] = {};

    for (int kt = 0; kt < SEQ; kt += 64) {
        // load K transposed ([d][kv]) and V ([kv][d]) — full 64 cols
        #pragma unroll
        for (int j = 0; j < 4; j++) {
            int c = lc + 16*j;
            float4 k4 = *(const float4*)(Kg + (kt + lr)*HD + c);
            KPs[(c+0)*64 + lr] = k4.x; KPs[(c+1)*64 + lr] = k4.y;
            KPs[(c+2)*64 + lr] = k4.z; KPs[(c+3)*64 + lr] = k4.w;
            *(float4*)&Vs[lr*64 + c] = *(const float4*)(Vg + (kt + lr)*HD + c);
        }
        __syncthreads();

        // scores S = Q K^T (already scaled)
        float s[4][4] = {};
        #pragma unroll 8
        for (int d = 0; d < 64; d++) {
            float a0 = Qs[ty*64 + d],      a1 = Qs[(ty+16)*64 + d];
            float a2 = Qs[(ty+32)*64 + d], a3 = Qs[(ty+48)*64 + d];
            float2 b01 = *(const float2*)&KPs[d*64 + 2*tx];
            float2 b23 = *(const float2*)&KPs[d*64 + 2*tx + 32];
            s[0][0]+=a0*b01.x; s[0][1]+=a0*b01.y; s[0][2]+=a0*b23.x; s[0][3]+=a0*b23.y;
            s[1][0]+=a1*b01.x; s[1][1]+=a1*b01.y; s[1][2]+=a1*b23.x; s[1][3]+=a1*b23.y;
            s[2][0]+=a2*b01.x; s[2][1]+=a2*b01.y; s[2][2]+=a2*b23.x; s[2][3]+=a2*b23.y;
            s[3][0]+=a3*b01.x; s[3][1]+=a3*b01.y; s[3][2]+=a3*b23.x; s[3][3]+=a3*b23.y;
        }
        __syncthreads();   // K reads done; KPs becomes P

        // online softmax (row stats across the 16-lane tx group)
        #pragma unroll
        for (int i = 0; i < 4; i++) {
            float mx = fmaxf(fmaxf(s[i][0], s[i][1]), fmaxf(s[i][2], s[i][3]));
            #pragma unroll
            for (int off = 8; off; off >>= 1)
                mx = fmaxf(mx, __shfl_xor_sync(0xffffffffu, mx, off));
            float mn = fmaxf(m_i[i], mx);
            float p0 = __expf(s[i][0]-mn), p1 = __expf(s[i][1]-mn);
            float p2 = __expf(s[i][2]-mn), p3 = __expf(s[i][3]-mn);
            float ls = p0 + p1 + p2 + p3;
            #pragma unroll
            for (int off = 8; off; off >>= 1)
                ls += __shfl_xor_sync(0xffffffffu, ls, off);
            float alpha = __expf(m_i[i] - mn);
            m_i[i] = mn;
            l_i[i] = l_i[i]*alpha + ls;
            o[i][0]*=alpha; o[i][1]*=alpha; o[i][2]*=alpha; o[i][3]*=alpha;
            int r = ty + 16*i;
            *(float2*)&KPs[r*64 + 2*tx]      = make_float2(p0, p1);
            *(float2*)&KPs[r*64 + 2*tx + 32] = make_float2(p2, p3);
        }
        __syncthreads();

        // O += P V
        #pragma unroll 8
        for (int k = 0; k < 64; k++) {
            float a0 = KPs[ty*64 + k],      a1 = KPs[(ty+16)*64 + k];
            float a2 = KPs[(ty+32)*64 + k], a3 = KPs[(ty+48)*64 + k];
            float2 b01 = *(const float2*)&Vs[k*64 + 2*tx];
            float2 b23 = *(const float2*)&Vs[k*64 + 2*tx + 32];
            o[0][0]+=a0*b01.x; o[0][1]+=a0*b01.y; o[0][2]+=a0*b23.x; o[0][3]+=a0*b23.y;
            o[1][0]+=a1*b01.x; o[1][1]+=a1*b01.y; o[1][2]+=a1*b23.x; o[1][3]+=a1*b23.y;
            o[2][0]+=a2*b01.x; o[2][1]+=a2*b01.y; o[2][2]+=a2*b23.x; o[2][3]+=a2*b23.y;
            o[3][0]+=a3*b01.x; o[3][1]+=a3*b01.y; o[3][2]+=a3*b23.x; o[3][3]+=a3*b23.y;
        }
        __syncthreads();
    }

    // write [B,S,H,hd] (row-major [B*S, D]) so O-proj is a plain NT GEMM
    const int b = bh >> 4, h = bh & 15;
    #pragma unroll
    for (int i = 0; i < 4; i++) {
        float inv = 1.0f / l_i[i];
        int srow = qt*64 + ty + 16*i;
        float* dst = g_att + ((b*SEQ + srow)*NH + h)*HD;
        *(float2*)&dst[2*tx]      = make_float2(o[i][0]*inv, o[i][1]*inv);
        *(float2*)&dst[2*tx + 32] = make_float2(o[i][2]*inv, o[i][3]*inv);
    }
}

// ---------------------------------------------------------------------------
extern "C" void kernel_launch(void* const* d_in, const int* in_sizes, int n_in,
                              void* d_out, int out_size)
{
    const float* q  = (const float*)d_in[0];
    const float* k  = (const float*)d_in[1];
    const float* v  = (const float*)d_in[2];
    const float* qw = (const float*)d_in[3];
    const float* qb = (const float*)d_in[4];
    const float* kw = (const float*)d_in[5];
    const float* kb = (const float*)d_in[6];
    const float* vw = (const float*)d_in[7];
    const float* vb = (const float*)d_in[8];
    const float* ow = (const float*)d_in[9];
    const float* ob = (const float*)d_in[10];
    float* out = (float*)d_out;

    rope_table_kernel<<<64, 1024>>>();

    dim3 gg(DIM/64, MROWS/64);   // (16, 64)
    gemm_nt_kernel<0><<<gg, 256>>>(q, qw, qb, nullptr);
    gemm_nt_kernel<1><<<gg, 256>>>(k, kw, kb, nullptr);
    gemm_nt_kernel<2><<<gg, 256>>>(v, vw, vb, nullptr);

    attn_kernel<<<dim3(SEQ/64, NB*NH), 256>>>();

    gemm_nt_kernel<3><<<gg, 256>>>(nullptr, ow, ob, out);
}

// round 3
// speedup vs baseline: 1.2140x; 1.2140x over previous
#include <cuda_runtime.h>

#define NB   2
#define SEQ  2048
#define DIM  1024
#define NH   16
#define HD   64
#define MROWS (NB*SEQ)   // 4096

// Scratch (allocation-free rule: __device__ globals)
__device__ float g_q[NB*NH*SEQ*HD];     // [B,H,S,hd]
__device__ float g_k[NB*NH*SEQ*HD];
__device__ float g_v[NB*NH*SEQ*HD];
__device__ float g_att[MROWS*DIM];      // [B,S,H*hd]
__device__ float g_cos[SEQ*(HD/2)];
__device__ float g_sin[SEQ*(HD/2)];

// ---------------------------------------------------------------------------
// Blackwell packed fp32-pair ops (FFMA2 reachable only via PTX f32x2)
// ---------------------------------------------------------------------------
__device__ __forceinline__ void f2fma(float2& c, float2 a, float2 b) {
    unsigned long long cc = *reinterpret_cast<unsigned long long*>(&c);
    unsigned long long aa = *reinterpret_cast<unsigned long long*>(&a);
    unsigned long long bb = *reinterpret_cast<unsigned long long*>(&b);
    asm("fma.rn.f32x2 %0, %1, %2, %0;" : "+l"(cc) : "l"(aa), "l"(bb));
    c = *reinterpret_cast<float2*>(&cc);
}
__device__ __forceinline__ void f2mul(float2& c, float2 a) {
    unsigned long long cc = *reinterpret_cast<unsigned long long*>(&c);
    unsigned long long aa = *reinterpret_cast<unsigned long long*>(&a);
    asm("mul.rn.f32x2 %0, %0, %1;" : "+l"(cc) : "l"(aa));
    c = *reinterpret_cast<float2*>(&cc);
}

// ---------------------------------------------------------------------------
// RoPE table: angle = s * theta^(-p/32), computed in double for accuracy.
// ---------------------------------------------------------------------------
__global__ void rope_table_kernel() {
    int i = blockIdx.x * blockDim.x + threadIdx.x;
    if (i >= SEQ * (HD/2)) return;
    int s = i >> 5;          // position
    int p = i & 31;          // pair index
    double inv = pow(10000.0, -(double)p / 32.0);
    double a = (double)s * inv;
    g_cos[i] = (float)cos(a);
    g_sin[i] = (float)sin(a);
}

// ---------------------------------------------------------------------------
// NT GEMM: C[m,n] = sum_k A[m,k] * W[n,k] + bias[n]
// BM=BN=128, BK=16, 256 threads, 8x8 micro-tile per thread, FFMA2 packed.
// Thread (tx,ty): rows {4ty..4ty+3, 64+4ty..64+4ty+3},
//                 cols {4tx..4tx+3, 64+4tx..64+4tx+3} (adjacent pairs -> RoPE)
// Smem stored k-major (As[k][m]) so microtile operands are float4 LDS.
// MODE 0/1: Q/K proj (+RoPE, scatter [B,H,S,hd]); 2: V; 3: O proj.
// ---------------------------------------------------------------------------
template<int MODE>
__global__ void __launch_bounds__(256, 2) gemm_nt_kernel(
        const float* __restrict__ A, const float* __restrict__ W,
        const float* __restrict__ bias, float* __restrict__ Cout)
{
    __shared__ __align__(16) float As[16][128];
    __shared__ __align__(16) float Bs[16][128];

    const int tid = threadIdx.x;
    const int tx = tid & 15, ty = tid >> 4;
    const int al_r = tid >> 1;          // 0..127
    const int al_c = (tid & 1) * 8;     // 0 or 8
    const int row0 = blockIdx.y << 7, col0 = blockIdx.x << 7;

    const float* Abase = (MODE == 3) ? (const float*)g_att : A;
    const float* Ap = Abase + (row0 + al_r) * DIM + al_c;
    const float* Wp = W + (col0 + al_r) * DIM + al_c;

    float2 acc[8][4];
    #pragma unroll
    for (int r = 0; r < 8; r++)
        #pragma unroll
        for (int p = 0; p < 4; p++) acc[r][p] = make_float2(0.f, 0.f);

    for (int k0 = 0; k0 < DIM; k0 += 16) {
        float4 av0 = *(const float4*)(Ap + k0);
        float4 av1 = *(const float4*)(Ap + k0 + 4);
        float4 wv0 = *(const float4*)(Wp + k0);
        float4 wv1 = *(const float4*)(Wp + k0 + 4);
        if (k0) __syncthreads();
        As[al_c+0][al_r] = av0.x; As[al_c+1][al_r] = av0.y;
        As[al_c+2][al_r] = av0.z; As[al_c+3][al_r] = av0.w;
        As[al_c+4][al_r] = av1.x; As[al_c+5][al_r] = av1.y;
        As[al_c+6][al_r] = av1.z; As[al_c+7][al_r] = av1.w;
        Bs[al_c+0][al_r] = wv0.x; Bs[al_c+1][al_r] = wv0.y;
        Bs[al_c+2][al_r] = wv0.z; Bs[al_c+3][al_r] = wv0.w;
        Bs[al_c+4][al_r] = wv1.x; Bs[al_c+5][al_r] = wv1.y;
        Bs[al_c+6][al_r] = wv1.z; Bs[al_c+7][al_r] = wv1.w;
        __syncthreads();
        #pragma unroll
        for (int kk = 0; kk < 16; kk++) {
            float4 A0 = *(const float4*)&As[kk][4*ty];
            float4 A1 = *(const float4*)&As[kk][4*ty + 64];
            float4 B0 = *(const float4*)&Bs[kk][4*tx];
            float4 B1 = *(const float4*)&Bs[kk][4*tx + 64];
            float2 bp[4] = { make_float2(B0.x,B0.y), make_float2(B0.z,B0.w),
                             make_float2(B1.x,B1.y), make_float2(B1.z,B1.w) };
            float ar[8] = {A0.x,A0.y,A0.z,A0.w,A1.x,A1.y,A1.z,A1.w};
            #pragma unroll
            for (int r = 0; r < 8; r++) {
                float2 a2 = make_float2(ar[r], ar[r]);
                #pragma unroll
                for (int p = 0; p < 4; p++) f2fma(acc[r][p], a2, bp[p]);
            }
        }
    }

    // Epilogue. acc[r][p]: row = row0 + 4ty + (r&3) + (r>=4?64:0)
    //                      cols = col0 + (p>=2?64:0) + 4tx + (p&1)*2, +1
    #pragma unroll
    for (int r = 0; r < 8; r++) {
        int m = row0 + 4*ty + (r & 3) + ((r & 4) ? 64 : 0);
        #pragma unroll
        for (int p = 0; p < 4; p++) {
            int n = col0 + ((p & 2) ? 64 : 0) + 4*tx + (p & 1)*2;
            float2 bv = *(const float2*)&bias[n];
            float e = acc[r][p].x + bv.x;
            float o = acc[r][p].y + bv.y;
            if (MODE == 3) {
                *(float2*)&Cout[m*DIM + n] = make_float2(e, o);
            } else {
                float* dst = (MODE == 0) ? g_q : (MODE == 1) ? g_k : g_v;
                int b = m >> 11;
                int s = m & (SEQ - 1);
                int d0 = n & 63;
                int h  = n >> 6;
                float re, im;
                if (MODE <= 1) {
                    float c  = g_cos[s*32 + (d0 >> 1)];
                    float sn = g_sin[s*32 + (d0 >> 1)];
                    re = e*c - o*sn;
                    im = e*sn + o*c;
                } else { re = e; im = o; }
                int idx = ((b*NH + h)*SEQ + s)*HD + d0;
                *(float2*)&dst[idx] = make_float2(re, im);
            }
        }
    }
}

// ---------------------------------------------------------------------------
// Flash attention: one CTA per (batch-head, 64-row q-tile), FFMA2 packed.
// Qs transposed [d][q] so QK^T a-operand is one LDS.128.
// KP dual-use: K^T [d][kv] for QK^T, then P [q][kv] for PV.
// Thread (tx,ty): rows {4ty..4ty+3}, cols {2tx,2tx+1} and {2tx+32,2tx+33}.
// ---------------------------------------------------------------------------
__global__ void __launch_bounds__(256) attn_kernel() {
    __shared__ __align__(16) float Qs[64*64];   // [d][q]
    __shared__ __align__(16) float KP[64*64];   // K^T [d][kv] -> P [q][kv]
    __shared__ __align__(16) float Vs[64*64];   // [kv][d]

    const int tid = threadIdx.x;
    const int tx = tid & 15, ty = tid >> 4;
    const int lr = tid >> 2, lc = (tid & 3) << 2;
    const int qt = blockIdx.x, bh = blockIdx.y;

    const float* Qg = g_q + (bh*SEQ + qt*64)*HD;
    const float* Kg = g_k + bh*SEQ*HD;
    const float* Vg = g_v + bh*SEQ*HD;

    {   // Q tile transposed + pre-scaled
        const float sc = 0.125f;
        #pragma unroll
        for (int j = 0; j < 4; j++) {
            int c = lc + 16*j;
            float4 q4 = *(const float4*)(Qg + lr*HD + c);
            Qs[(c+0)*64 + lr] = q4.x*sc; Qs[(c+1)*64 + lr] = q4.y*sc;
            Qs[(c+2)*64 + lr] = q4.z*sc; Qs[(c+3)*64 + lr] = q4.w*sc;
        }
    }

    float m_i[4] = {-1e30f, -1e30f, -1e30f, -1e30f};
    float l_i[4] = {};
    float2 o01[4] = {}, o23[4] = {};   // [row r], col pairs (2tx,2tx+1)/(+32,+33)

    for (int kt = 0; kt < SEQ; kt += 64) {
        #pragma unroll
        for (int j = 0; j < 4; j++) {
            int c = lc + 16*j;
            float4 k4 = *(const float4*)(Kg + (kt + lr)*HD + c);
            KP[(c+0)*64 + lr] = k4.x; KP[(c+1)*64 + lr] = k4.y;
            KP[(c+2)*64 + lr] = k4.z; KP[(c+3)*64 + lr] = k4.w;
            *(float4*)&Vs[lr*64 + c] = *(const float4*)(Vg + (kt + lr)*HD + c);
        }
        __syncthreads();

        // S = Q K^T (pre-scaled)
        float2 s01[4] = {}, s23[4] = {};
        #pragma unroll 4
        for (int d = 0; d < 64; d++) {
            float4 a4  = *(const float4*)&Qs[d*64 + 4*ty];
            float2 b01 = *(const float2*)&KP[d*64 + 2*tx];
            float2 b23 = *(const float2*)&KP[d*64 + 2*tx + 32];
            float ar[4] = {a4.x, a4.y, a4.z, a4.w};
            #pragma unroll
            for (int r = 0; r < 4; r++) {
                float2 a2 = make_float2(ar[r], ar[r]);
                f2fma(s01[r], a2, b01);
                f2fma(s23[r], a2, b23);
            }
        }
        __syncthreads();   // K^T reads done; KP becomes P

        // online softmax (row stats across the 16-lane tx group)
        #pragma unroll
        for (int r = 0; r < 4; r++) {
            float mx = fmaxf(fmaxf(s01[r].x, s01[r].y), fmaxf(s23[r].x, s23[r].y));
            #pragma unroll
            for (int off = 8; off; off >>= 1)
                mx = fmaxf(mx, __shfl_xor_sync(0xffffffffu, mx, off));
            float mn = fmaxf(m_i[r], mx);
            float p00 = __expf(s01[r].x - mn), p01 = __expf(s01[r].y - mn);
            float p10 = __expf(s23[r].x - mn), p11 = __expf(s23[r].y - mn);
            float ls = p00 + p01 + p10 + p11;
            #pragma unroll
            for (int off = 8; off; off >>= 1)
                ls += __shfl_xor_sync(0xffffffffu, ls, off);
            float alpha = __expf(m_i[r] - mn);
            m_i[r] = mn;
            l_i[r] = l_i[r]*alpha + ls;
            float2 al2 = make_float2(alpha, alpha);
            f2mul(o01[r], al2);
            f2mul(o23[r], al2);
            int rg = 4*ty + r;
            *(float2*)&KP[rg*64 + 2*tx]      = make_float2(p00, p01);
            *(float2*)&KP[rg*64 + 2*tx + 32] = make_float2(p10, p11);
        }
        __syncthreads();

        // O += P V
        #pragma unroll 4
        for (int k = 0; k < 64; k++) {
            float2 b01 = *(const float2*)&Vs[k*64 + 2*tx];
            float2 b23 = *(const float2*)&Vs[k*64 + 2*tx + 32];
            float pr[4] = { KP[(4*ty+0)*64 + k], KP[(4*ty+1)*64 + k],
                            KP[(4*ty+2)*64 + k], KP[(4*ty+3)*64 + k] };
            #pragma unroll
            for (int r = 0; r < 4; r++) {
                float2 a2 = make_float2(pr[r], pr[r]);
                f2fma(o01[r], a2, b01);
                f2fma(o23[r], a2, b23);
            }
        }
        __syncthreads();
    }

    // write [B,S,H,hd] (row-major [B*S, D]) so O-proj is a plain NT GEMM
    const int b = bh >> 4, h = bh & 15;
    #pragma unroll
    for (int r = 0; r < 4; r++) {
        float inv = 1.0f / l_i[r];
        int srow = qt*64 + 4*ty + r;
        float* dst = g_att + ((b*SEQ + srow)*NH + h)*HD;
        *(float2*)&dst[2*tx]      = make_float2(o01[r].x*inv, o01[r].y*inv);
        *(float2*)&dst[2*tx + 32] = make_float2(o23[r].x*inv, o23[r].y*inv);
    }
}

// ---------------------------------------------------------------------------
extern "C" void kernel_launch(void* const* d_in, const int* in_sizes, int n_in,
                              void* d_out, int out_size)
{
    const float* q  = (const float*)d_in[0];
    const float* k  = (const float*)d_in[1];
    const float* v  = (const float*)d_in[2];
    const float* qw = (const float*)d_in[3];
    const float* qb = (const float*)d_in[4];
    const float* kw = (const float*)d_in[5];
    const float* kb = (const float*)d_in[6];
    const float* vw = (const float*)d_in[7];
    const float* vb = (const float*)d_in[8];
    const float* ow = (const float*)d_in[9];
    const float* ob = (const float*)d_in[10];
    float* out = (float*)d_out;

    rope_table_kernel<<<64, 1024>>>();

    dim3 gg(DIM/128, MROWS/128);   // (8, 32)
    gemm_nt_kernel<0><<<gg, 256>>>(q, qw, qb, nullptr);
    gemm_nt_kernel<1><<<gg, 256>>>(k, kw, kb, nullptr);
    gemm_nt_kernel<2><<<gg, 256>>>(v, vw, vb, nullptr);

    attn_kernel<<<dim3(SEQ/64, NB*NH), 256>>>();

    gemm_nt_kernel<3><<<gg, 256>>>(nullptr, ow, ob, out);
}